// round 11
// baseline (speedup 1.0000x reference)
#include <cuda_runtime.h>
#include <math.h>
#include <stdint.h>

#define KCMAX 95
#define NUM_DET 100
#define SCORE_THRESH 0.05f
#define NMS_THRESH 0.5f
#define MIN_SIZE 1.0f
#define BBOX_CLIP 4.135166556742356f
#define NMS_THREADS 512
#define NWARPS 16
#define CAP 2048
#define NBKT 64
#define BCAP 256
#define NBINS 576
#define HBASE 0x3D4C             // bits(0.05f) >> 16
#define CHUNK_TARGET 160
#define SELCAP 512

// ---------------- device scratch ----------------
__device__ float  d_row_max0;
__device__ float  d_row_den0;
__device__ int    d_cnt2[KCMAX][NBKT];
__device__ float4 d_cand_box[KCMAX][NBKT][BCAP];
__device__ float2 d_cand_sg[KCMAX][NBKT][BCAP];
__device__ int    d_ndet[KCMAX];
__device__ int    d_keep_gi[KCMAX][NUM_DET];
__device__ float  d_keep_sc[KCMAX][NUM_DET];
__device__ float4 d_keep_box[KCMAX][NUM_DET];

// ---------------- helpers ----------------
__device__ __forceinline__ void decode_box(
    float d0, float d1, float d2, float d3,
    float bx1, float by1, float bx2, float by2,
    float& ox1, float& oy1, float& ox2, float& oy2)
{
    float w  = bx2 - bx1;
    float h  = by2 - by1;
    float cx = bx1 + 0.5f * w;
    float cy = by1 + 0.5f * h;
    float dx = d0 / 10.0f;
    float dy = d1 / 10.0f;
    float dw = fminf(d2 / 5.0f, BBOX_CLIP);
    float dh = fminf(d3 / 5.0f, BBOX_CLIP);
    float pcx = dx * w + cx;
    float pcy = dy * h + cy;
    float pw  = expf(dw) * w;
    float ph  = expf(dh) * h;
    ox1 = pcx - 0.5f * pw;
    oy1 = pcy - 0.5f * ph;
    ox2 = pcx + 0.5f * pw;
    oy2 = pcy + 0.5f * ph;
}

__device__ __forceinline__ float clipf(float v, float hi) {
    return fminf(fmaxf(v, 0.0f), hi);
}

__device__ __forceinline__ bool iou_over(const float4& a, float aarea,
                                         const float4& b, float barea)
{
    float ix1 = fmaxf(a.x, b.x);
    float iy1 = fmaxf(a.y, b.y);
    float ix2 = fminf(a.z, b.z);
    float iy2 = fminf(a.w, b.w);
    float iw = fmaxf(0.0f, ix2 - ix1);
    float ih = fmaxf(0.0f, iy2 - iy1);
    float inter = iw * ih;
    float iou = inter / (aarea + barea - inter + 1e-9f);
    return iou > NMS_THRESH;
}

__device__ __forceinline__ unsigned long long u64max(unsigned long long a, unsigned long long b) { return a > b ? a : b; }
__device__ __forceinline__ unsigned long long u64min(unsigned long long a, unsigned long long b) { return a < b ? a : b; }

// ---------------- kernel 1: softmax + decode + filter + bucketed compact ----------------
__global__ __launch_bounds__(256) void score_extract(
    const float* __restrict__ logit,
    const float* __restrict__ breg,
    const float* __restrict__ prop,
    const int* __restrict__ p_ih,
    const int* __restrict__ p_iw,
    int N, int C)
{
    int warp = (blockIdx.x * blockDim.x + threadIdx.x) >> 5;
    int lane = threadIdx.x & 31;
    if (warp >= N) return;

    const float* row = logit + (size_t)warp * C;

    float lv[3];
    float mx = -INFINITY;
#pragma unroll
    for (int j = 0; j < 3; j++) {
        int c = lane + 32 * j;
        lv[j] = (c < C) ? row[c] : -INFINITY;
        mx = fmaxf(mx, lv[j]);
    }
#pragma unroll
    for (int o = 16; o; o >>= 1) mx = fmaxf(mx, __shfl_xor_sync(0xFFFFFFFFu, mx, o));

    float ev[3];
    float s = 0.0f;
#pragma unroll
    for (int j = 0; j < 3; j++) {
        int c = lane + 32 * j;
        ev[j] = (c < C) ? expf(lv[j] - mx) : 0.0f;
        s += ev[j];
    }
#pragma unroll
    for (int o = 16; o; o >>= 1) s += __shfl_xor_sync(0xFFFFFFFFu, s, o);

    if (warp == 0 && lane == 0) { d_row_max0 = mx; d_row_den0 = s; }
    float inv = 1.0f / s;

    float W = (float)(*p_iw);
    float H = (float)(*p_ih);
    float4 p = ((const float4*)prop)[warp];
    int bkt = blockIdx.x & (NBKT - 1);

#pragma unroll
    for (int j = 0; j < 3; j++) {
        int c = lane + 32 * j;
        if (c <= 0 || c >= C) continue;
        float pscore = ev[j] * inv;
        if (pscore >= SCORE_THRESH) {
            const float4 dd = *(const float4*)(breg + ((size_t)warp * C + c) * 4);
            float x1, y1, x2, y2;
            decode_box(dd.x, dd.y, dd.z, dd.w, p.x, p.y, p.z, p.w, x1, y1, x2, y2);
            x1 = clipf(x1, W); x2 = clipf(x2, W);
            y1 = clipf(y1, H); y2 = clipf(y2, H);
            if ((x2 - x1) >= MIN_SIZE && (y2 - y1) >= MIN_SIZE) {
                int cls = c - 1;
                int pos = atomicAdd(&d_cnt2[cls][bkt], 1);
                if (pos < BCAP) {
                    d_cand_box[cls][bkt][pos] = make_float4(x1, y1, x2, y2);
                    d_cand_sg[cls][bkt][pos]  = make_float2(pscore, __int_as_float(warp));
                }
            }
        }
    }
}

// ---------------- kernel 2: NMS selection (512 threads, 32-wide tiles) ----------------
__global__ __launch_bounds__(NMS_THREADS) void nms_select_kernel()
{
    int cls = blockIdx.x;
    int tid = threadIdx.x;
    int laneId = tid & 31;
    int warpId = tid >> 5;

    __shared__ int    s_off[NBKT + 1];
    __shared__ unsigned long long s_key[CAP];
    __shared__ int    hist[NBINS];
    __shared__ unsigned long long s_sel[SELCAP];
    __shared__ float4 s_rbox[SELCAP];
    __shared__ float  s_rarea[SELCAP];
    __shared__ float4 a_box[NUM_DET];
    __shared__ float  a_area[NUM_DET];
    __shared__ int    a_gi[NUM_DET];
    __shared__ float  a_sc[NUM_DET];
    __shared__ int    s_cut, s_chunkn, s_nacc, s_selcnt;
    __shared__ int    s_pairm[2][32];
    __shared__ int    s_supm[2][32];

    // ---- bucket prefix (warp 0) ----
    if (warpId == 0) {
        int c0 = min(d_cnt2[cls][2 * laneId],     BCAP);
        int c1 = min(d_cnt2[cls][2 * laneId + 1], BCAP);
        int pair = c0 + c1;
        int incl = pair;
#pragma unroll
        for (int o = 1; o < 32; o <<= 1) {
            int v = __shfl_up_sync(0xFFFFFFFFu, incl, o);
            if (laneId >= o) incl += v;
        }
        s_off[2 * laneId]     = incl - pair;
        s_off[2 * laneId + 1] = incl - c1;
        if (laneId == 31) s_off[NBKT] = incl;
    }
    for (int i = tid; i < NBINS; i += NMS_THREADS) hist[i] = 0;
    if (tid == 0) s_nacc = 0;
    __syncthreads();

    if (tid < NBKT) d_cnt2[cls][tid] = 0;
    int cnt = s_off[NBKT];
    if (cnt > CAP) cnt = CAP;

    // ---- bucket-direct key load + histogram (16 warps: 4 buckets each) ----
    for (int b = warpId; b < NBKT; b += NWARPS) {
        int off = s_off[b];
        int c   = s_off[b + 1] - off;
        for (int e = laneId; e < c; e += 32) {
            int i = off + e;
            if (i >= CAP) break;
            float2 sg = d_cand_sg[cls][b][e];
            unsigned u = __float_as_uint(sg.x);
            unsigned gi_inv = 0xFFFFu - (unsigned)__float_as_int(sg.y);
            s_key[i] = ((unsigned long long)u << 32) |
                       ((unsigned long long)gi_inv << 16) |
                       (unsigned long long)(unsigned)((b << 8) | e);
            int bin = min((int)(u >> 16) - HBASE, NBINS - 1);
            atomicAdd(&hist[bin], 1);
        }
    }
    __syncthreads();

    // ---- incremental descending-score chunks ----
    float4 rb[4];
    float  ra[4];
#pragma unroll
    for (int s = 0; s < 4; s++) { rb[s] = make_float4(0,0,0,0); ra[s] = 0.0f; }
    int naccr = 0;

    int hi_cut = NBINS;
    bool fb = false;

    while (naccr < NUM_DET && hi_cut > 0 && !fb) {
        if (warpId == 0) {
            int acc = 0, cut = 0, chn = 0;
            bool found = false;
            int baseStart = ((hi_cut - 1) >> 5) << 5;
            for (int base = baseStart; base >= 0; base -= 32) {
                int bin = base + laneId;
                int v = (bin < hi_cut) ? hist[bin] : 0;
                int tot = v;
#pragma unroll
                for (int o = 16; o; o >>= 1) tot += __shfl_xor_sync(0xFFFFFFFFu, tot, o);
                if (acc + tot >= CHUNK_TARGET) {
                    int suf = v;
#pragma unroll
                    for (int o = 1; o < 32; o <<= 1) {
                        int t = __shfl_down_sync(0xFFFFFFFFu, suf, o);
                        if (laneId + o < 32) suf += t;
                    }
                    unsigned bal = __ballot_sync(0xFFFFFFFFu, acc + suf >= CHUNK_TARGET);
                    int L = 31 - __clz(bal);
                    cut = base + L;
                    chn = acc + __shfl_sync(0xFFFFFFFFu, suf, L);
                    found = true;
                    break;
                }
                acc += tot;
            }
            if (!found) { cut = 0; chn = acc; }
            if (laneId == 0) { s_cut = cut; s_chunkn = chn; s_selcnt = 0; }
        }
        __syncthreads();
        int cutv = s_cut;
        int chn  = s_chunkn;

        if (chn > SELCAP) { fb = true; break; }

        if (chn > 0) {
            // -- gather chunk keys --
            for (int i = tid; i < cnt; i += NMS_THREADS) {
                unsigned long long k = s_key[i];
                int bin = min((int)((unsigned)(k >> 32) >> 16) - HBASE, NBINS - 1);
                if (bin >= cutv && bin < hi_cut) {
                    int pos = atomicAdd(&s_selcnt, 1);
                    s_sel[pos] = k;
                }
            }
            __syncthreads();

            if (chn <= 256) {
                // register bitonic 256 on threads 0-255; uniform barriers for all 512
                unsigned long long kr = 0ull;
                if (tid < 256 && tid < chn) kr = s_sel[tid];
#pragma unroll
                for (int k = 2; k <= 256; k <<= 1) {
#pragma unroll
                    for (int j = k >> 1; j > 0; j >>= 1) {
                        if (j >= 32) {
                            if (tid < 256) s_sel[tid] = kr;
                            __syncthreads();
                            unsigned long long o = (tid < 256) ? s_sel[tid ^ j] : 0ull;
                            __syncthreads();
                            bool keepMax = ((tid & k) == 0) == ((tid & j) == 0);
                            if (tid < 256) kr = keepMax ? u64max(kr, o) : u64min(kr, o);
                        } else {
                            unsigned long long o = __shfl_xor_sync(0xFFFFFFFFu, kr, j);
                            bool keepMax = ((tid & k) == 0) == ((tid & j) == 0);
                            kr = keepMax ? u64max(kr, o) : u64min(kr, o);
                        }
                    }
                }
                if (tid < 256) s_sel[tid] = kr;
                __syncthreads();
            } else {
                for (int i = chn + tid; i < SELCAP; i += NMS_THREADS) s_sel[i] = 0ull;
                __syncthreads();
                for (int k = 2; k <= SELCAP; k <<= 1) {
                    for (int j = k >> 1; j > 0; j >>= 1) {
                        for (int idx = tid; idx < SELCAP; idx += NMS_THREADS) {
                            int l = idx ^ j;
                            if (l > idx) {
                                unsigned long long a = s_sel[idx];
                                unsigned long long b = s_sel[l];
                                bool up = ((idx & k) == 0);
                                if (up ? (a < b) : (a > b)) { s_sel[idx] = b; s_sel[l] = a; }
                            }
                        }
                        __syncthreads();
                    }
                }
            }

            // -- box fetch by rank --
            for (int r = tid; r < chn; r += NMS_THREADS) {
                int slot = (int)(s_sel[r] & 0xFFFFu);
                float4 bx = d_cand_box[cls][slot >> 8][slot & 255];
                s_rbox[r]  = bx;
                s_rarea[r] = (bx.z - bx.x) * (bx.w - bx.y);
            }
            __syncthreads();

            // -- 32-wide single-barrier tiles: warp w owns candidates tb+w, tb+16+w --
            for (int tb = 0; tb < chn && naccr < NUM_DET; tb += 32) {
                int buf = (tb >> 5) & 1;
                int i1 = tb + warpId;
                int i2 = tb + 16 + warpId;

                bool sup1 = false, pair1 = false;
                bool sup2 = false, pair2 = false;
                if (i1 < chn) {
                    float4 b1 = s_rbox[i1];
                    float ca1 = s_rarea[i1];
#pragma unroll
                    for (int s = 0; s < 4; s++) {
                        int j = s * 32 + laneId;
                        if (j < naccr && iou_over(rb[s], ra[s], b1, ca1)) sup1 = true;
                    }
                    if (laneId < warpId)
                        pair1 = iou_over(s_rbox[tb + laneId], s_rarea[tb + laneId], b1, ca1);
                }
                if (i2 < chn) {
                    float4 b2 = s_rbox[i2];
                    float ca2 = s_rarea[i2];
#pragma unroll
                    for (int s = 0; s < 4; s++) {
                        int j = s * 32 + laneId;
                        if (j < naccr && iou_over(rb[s], ra[s], b2, ca2)) sup2 = true;
                    }
                    if (laneId < 16 + warpId)
                        pair2 = iou_over(s_rbox[tb + laneId], s_rarea[tb + laneId], b2, ca2);
                }
                unsigned bal1 = __ballot_sync(0xFFFFFFFFu, pair1) & ((1u << warpId) - 1u);
                unsigned bal2 = __ballot_sync(0xFFFFFFFFu, pair2) & ((1u << (16 + warpId)) - 1u);
                bool sa1 = __any_sync(0xFFFFFFFFu, sup1);
                bool sa2 = __any_sync(0xFFFFFFFFu, sup2);
                if (laneId == 0) {
                    s_pairm[buf][warpId]      = (int)bal1;
                    s_supm[buf][warpId]       = sa1 ? 1 : 0;
                    s_pairm[buf][16 + warpId] = (int)bal2;
                    s_supm[buf][16 + warpId]  = sa2 ? 1 : 0;
                }
                __syncthreads();       // the only barrier in the tile

                // redundant resolve (identical in every thread)
                unsigned kept = 0;
                int newn = 0;
#pragma unroll
                for (int t = 0; t < 32; t++) {
                    if (tb + t < chn && naccr + newn < NUM_DET) {
                        if (!s_supm[buf][t] && !((unsigned)s_pairm[buf][t] & kept)) {
                            kept |= 1u << t;
                            newn++;
                        }
                    }
                }

                // append accepted (warp 0, lanes 0-31)
                if (warpId == 0 && ((kept >> laneId) & 1u)) {
                    int pos = naccr + __popc(kept & ((1u << laneId) - 1u));
                    int ii = tb + laneId;
                    unsigned long long k = s_sel[ii];
                    a_box[pos]  = s_rbox[ii];
                    a_area[pos] = s_rarea[ii];
                    a_gi[pos]   = (int)(0xFFFFu - ((unsigned)(k >> 16) & 0xFFFFu));
                    a_sc[pos]   = __uint_as_float((unsigned)(k >> 32));
                }

                // self-refresh replicas straight from s_rbox (no barrier needed)
                int rank = 0;
#pragma unroll
                for (int t = 0; t < 32; t++) {
                    if ((kept >> t) & 1u) {
                        int pos = naccr + rank;
                        if ((pos & 31) == laneId) {
                            int sl = pos >> 5;
                            float4 bb = s_rbox[tb + t];
                            float  aa = s_rarea[tb + t];
#pragma unroll
                            for (int q = 0; q < 4; q++) if (q == sl) { rb[q] = bb; ra[q] = aa; }
                        }
                        rank++;
                    }
                }
                naccr += newn;
            }
            if (tid == 0) s_nacc = naccr;
            __syncthreads();
        }

        hi_cut = cutv;
        __syncthreads();
    }

    if (fb) {
        // ---- exact fallback (pathological only): full sort + chunked serial scan ----
        int n2 = 1;
        while (n2 < cnt) n2 <<= 1;
        for (int i = cnt + tid; i < n2; i += NMS_THREADS) s_key[i] = 0ull;
        if (tid == 0) s_nacc = 0;
        __syncthreads();
        for (int k = 2; k <= n2; k <<= 1) {
            for (int j = k >> 1; j > 0; j >>= 1) {
                for (int idx = tid; idx < n2; idx += NMS_THREADS) {
                    int l = idx ^ j;
                    if (l > idx) {
                        unsigned long long a = s_key[idx];
                        unsigned long long b = s_key[l];
                        bool up = ((idx & k) == 0);
                        if (up ? (a < b) : (a > b)) { s_key[idx] = b; s_key[l] = a; }
                    }
                }
                __syncthreads();
            }
        }
        for (int cs = 0; cs < cnt; cs += SELCAP) {
            if (s_nacc >= NUM_DET) break;
            int ce = min(cnt, cs + SELCAP);
            for (int r = cs + tid; r < ce; r += NMS_THREADS) {
                int slot = (int)(s_key[r] & 0xFFFFu);
                float4 bx = d_cand_box[cls][slot >> 8][slot & 255];
                s_rbox[r - cs]  = bx;
                s_rarea[r - cs] = (bx.z - bx.x) * (bx.w - bx.y);
            }
            __syncthreads();
            if (warpId == 0) {
                int nacc = s_nacc;
                for (int i = cs; i < ce && nacc < NUM_DET; i++) {
                    unsigned long long k = s_key[i];
                    float4 b = s_rbox[i - cs];
                    float carea = s_rarea[i - cs];
                    bool sup = false;
#pragma unroll
                    for (int q = 0; q < 4; q++) {
                        int j = laneId + q * 32;
                        if (j < nacc && iou_over(a_box[j], a_area[j], b, carea)) sup = true;
                    }
                    if (!__any_sync(0xFFFFFFFFu, sup)) {
                        if (laneId == 0) {
                            a_box[nacc]  = b;
                            a_area[nacc] = carea;
                            a_gi[nacc]   = (int)(0xFFFFu - ((unsigned)(k >> 16) & 0xFFFFu));
                            a_sc[nacc]   = __uint_as_float((unsigned)(k >> 32));
                        }
                        nacc++;
                        __syncwarp();
                    }
                }
                if (laneId == 0) s_nacc = nacc;
            }
            __syncthreads();
        }
    }
    __syncthreads();
    int ndet = s_nacc;

    // ---- publish keep-list to global ----
    if (tid == 0) d_ndet[cls] = ndet;
    for (int d = tid; d < NUM_DET; d += NMS_THREADS) {
        if (d < ndet) {
            d_keep_gi[cls][d]  = a_gi[d];
            d_keep_sc[cls][d]  = a_sc[d];
            d_keep_box[cls][d] = a_box[d];
        } else {
            d_keep_gi[cls][d]  = 0;
            d_keep_sc[cls][d]  = 0.0f;
            d_keep_box[cls][d] = make_float4(0, 0, 0, 0);
        }
    }
}

// ---------------- kernel 3: gather + trajectory decode + outputs ----------------
__global__ __launch_bounds__(128) void output_kernel(
    const float* __restrict__ logit,
    const float* __restrict__ breg,
    const float* __restrict__ treg,
    const float* __restrict__ prop,
    const int* __restrict__ p_ih,
    const int* __restrict__ p_iw,
    float* __restrict__ out,
    int N, int C, int T, int M)
{
    int m = blockIdx.x * blockDim.x + threadIdx.x;
    if (m >= M) return;

    int cls = m / NUM_DET;
    int d   = m - cls * NUM_DET;
    int clabel = cls + 1;

    int ndet = d_ndet[cls];
    bool v = (d < ndet);
    int g = v ? d_keep_gi[cls][d] : 0;

    int ihv = *p_ih;
    int iwv = *p_iw;
    float4 p = ((const float4*)prop)[g];
    const float4 td0 = *(const float4*)(treg + (((size_t)0 * N + g) * C + clabel) * 4);
    const float4 td1 = *(const float4*)(treg + (((size_t)1 * N + g) * C + clabel) * 4);
    const float4 td2 = *(const float4*)(treg + (((size_t)2 * N + g) * C + clabel) * 4);

    float W = (float)iwv;
    float H = (float)ihv;

    float4 obox;
    float scv;
    if (v) {
        obox = d_keep_box[cls][d];
        scv  = d_keep_sc[cls][d];
    } else {
        // jnp.argmax(all -inf) = 0: emit row-0 data for this class, valid=0
        float lg  = logit[clabel];
        scv = expf(lg - d_row_max0) / d_row_den0;
        const float4 dd = *(const float4*)(breg + (size_t)clabel * 4);
        float x1, y1, x2, y2;
        decode_box(dd.x, dd.y, dd.z, dd.w, p.x, p.y, p.z, p.w, x1, y1, x2, y2);
        obox = make_float4(clipf(x1, W), clipf(y1, H), clipf(x2, W), clipf(y2, H));
    }

    size_t OFF_LBL = (size_t)M * 4;
    size_t OFF_SC  = OFF_LBL + M;
    size_t OFF_FUT = OFF_SC + M;
    size_t OFF_VAL = OFF_FUT + (size_t)T * M * 4;

    ((float4*)out)[m] = obox;
    out[OFF_LBL + m] = (float)clabel;
    out[OFF_SC + m]  = scv;
    out[OFF_VAL + m] = v ? 1.0f : 0.0f;

    float cx1 = p.x, cy1 = p.y, cx2 = p.z, cy2 = p.w;
    float4 tds[3] = {td0, td1, td2};
#pragma unroll
    for (int t = 0; t < 3; t++) {
        float nx1, ny1, nx2, ny2;
        decode_box(tds[t].x, tds[t].y, tds[t].z, tds[t].w,
                   cx1, cy1, cx2, cy2, nx1, ny1, nx2, ny2);
        float4 of = make_float4(clipf(nx1, W), clipf(ny1, H), clipf(nx2, W), clipf(ny2, H));
        ((float4*)(out + OFF_FUT))[(size_t)t * M + m] = of;
        cx1 = nx1; cy1 = ny1; cx2 = nx2; cy2 = ny2;
    }
}

// ---------------- launch ----------------
extern "C" void kernel_launch(void* const* d_in, const int* in_sizes, int n_in,
                              void* d_out, int out_size)
{
    const float* logit = (const float*)d_in[0];
    const float* breg  = (const float*)d_in[1];
    const float* treg  = (const float*)d_in[2];
    const float* prop  = (const float*)d_in[3];
    const int*   p_ih  = (const int*)d_in[4];
    const int*   p_iw  = (const int*)d_in[5];

    int N = in_sizes[3] / 4;
    int C = in_sizes[0] / N;
    int T = in_sizes[2] / in_sizes[1];
    int KC = C - 1;
    int M = KC * NUM_DET;

    int warpsPerBlock = 8;
    int blocks = (N + warpsPerBlock - 1) / warpsPerBlock;
    score_extract<<<blocks, 256>>>(logit, breg, prop, p_ih, p_iw, N, C);

    nms_select_kernel<<<KC, NMS_THREADS>>>();

    output_kernel<<<(M + 127) / 128, 128>>>(logit, breg, treg, prop, p_ih, p_iw,
                                            (float*)d_out, N, C, T, M);
}

// round 12
// speedup vs baseline: 1.0668x; 1.0668x over previous
#include <cuda_runtime.h>
#include <math.h>
#include <stdint.h>

#define KCMAX 95
#define NUM_DET 100
#define SCORE_THRESH 0.05f
#define NMS_THRESH 0.5f
#define MIN_SIZE 1.0f
#define BBOX_CLIP 4.135166556742356f
#define NMS_THREADS 256
#define CAP 2048
#define NBKT 64
#define BCAP 256
#define NBINS 576
#define HBASE 0x3D4C             // bits(0.05f) >> 16
#define CHUNK_TARGET 224
#define SELCAP 512
#define MIN_GRID 148             // pad grid to defeat low-grid issue throttle

// ---------------- device scratch ----------------
__device__ float  d_row_max0;
__device__ float  d_row_den0;
__device__ int    d_cnt2[KCMAX][NBKT];
__device__ float4 d_cand_box[KCMAX][NBKT][BCAP];
__device__ float2 d_cand_sg[KCMAX][NBKT][BCAP];

// ---------------- helpers ----------------
__device__ __forceinline__ void decode_box(
    float d0, float d1, float d2, float d3,
    float bx1, float by1, float bx2, float by2,
    float& ox1, float& oy1, float& ox2, float& oy2)
{
    float w  = bx2 - bx1;
    float h  = by2 - by1;
    float cx = bx1 + 0.5f * w;
    float cy = by1 + 0.5f * h;
    float dx = d0 / 10.0f;
    float dy = d1 / 10.0f;
    float dw = fminf(d2 / 5.0f, BBOX_CLIP);
    float dh = fminf(d3 / 5.0f, BBOX_CLIP);
    float pcx = dx * w + cx;
    float pcy = dy * h + cy;
    float pw  = expf(dw) * w;
    float ph  = expf(dh) * h;
    ox1 = pcx - 0.5f * pw;
    oy1 = pcy - 0.5f * ph;
    ox2 = pcx + 0.5f * pw;
    oy2 = pcy + 0.5f * ph;
}

__device__ __forceinline__ float clipf(float v, float hi) {
    return fminf(fmaxf(v, 0.0f), hi);
}

__device__ __forceinline__ bool iou_over(const float4& a, float aarea,
                                         const float4& b, float barea)
{
    float ix1 = fmaxf(a.x, b.x);
    float iy1 = fmaxf(a.y, b.y);
    float ix2 = fminf(a.z, b.z);
    float iy2 = fminf(a.w, b.w);
    float iw = fmaxf(0.0f, ix2 - ix1);
    float ih = fmaxf(0.0f, iy2 - iy1);
    float inter = iw * ih;
    float iou = inter / (aarea + barea - inter + 1e-9f);
    return iou > NMS_THRESH;
}

__device__ __forceinline__ unsigned long long u64max(unsigned long long a, unsigned long long b) { return a > b ? a : b; }
__device__ __forceinline__ unsigned long long u64min(unsigned long long a, unsigned long long b) { return a < b ? a : b; }

// ---------------- kernel 1: softmax + decode + filter + bucketed compact ----------------
// CT > 0: compile-time class count (fast path). CT == 0: runtime C (fallback).
template <int CT>
__global__ __launch_bounds__(256) void score_extract_t(
    const float* __restrict__ logit,
    const float* __restrict__ breg,
    const float* __restrict__ prop,
    const int* __restrict__ p_ih,
    const int* __restrict__ p_iw,
    int N, int Crt)
{
    const int C = (CT > 0) ? CT : Crt;
    int warp = (blockIdx.x * blockDim.x + threadIdx.x) >> 5;
    int lane = threadIdx.x & 31;
    if (warp >= N) return;

    const float* row = logit + (size_t)warp * C;

    float lv[3];
    float mx = -INFINITY;
#pragma unroll
    for (int j = 0; j < 3; j++) {
        int c = lane + 32 * j;
        lv[j] = (c < C) ? row[c] : -INFINITY;
        mx = fmaxf(mx, lv[j]);
    }
#pragma unroll
    for (int o = 16; o; o >>= 1) mx = fmaxf(mx, __shfl_xor_sync(0xFFFFFFFFu, mx, o));

    float ev[3];
    float s = 0.0f;
#pragma unroll
    for (int j = 0; j < 3; j++) {
        int c = lane + 32 * j;
        ev[j] = (c < C) ? expf(lv[j] - mx) : 0.0f;
        s += ev[j];
    }
#pragma unroll
    for (int o = 16; o; o >>= 1) s += __shfl_xor_sync(0xFFFFFFFFu, s, o);

    if (warp == 0 && lane == 0) { d_row_max0 = mx; d_row_den0 = s; }
    float inv = 1.0f / s;

    // merged candidate mask (identical selection: ev*inv >= 0.05)
    unsigned pm = 0;
#pragma unroll
    for (int j = 0; j < 3; j++) {
        int c = lane + 32 * j;
        if (c > 0 && c < C && ev[j] * inv >= SCORE_THRESH) pm |= 1u << j;
    }

    if (pm) {
        float W = (float)(*p_iw);
        float H = (float)(*p_ih);
        float4 p = ((const float4*)prop)[warp];
        int bkt = blockIdx.x & (NBKT - 1);
#pragma unroll
        for (int j = 0; j < 3; j++) {
            if (!(pm & (1u << j))) continue;
            int c = lane + 32 * j;
            const float4 dd = *(const float4*)(breg + ((size_t)warp * C + c) * 4);
            float x1, y1, x2, y2;
            decode_box(dd.x, dd.y, dd.z, dd.w, p.x, p.y, p.z, p.w, x1, y1, x2, y2);
            x1 = clipf(x1, W); x2 = clipf(x2, W);
            y1 = clipf(y1, H); y2 = clipf(y2, H);
            if ((x2 - x1) >= MIN_SIZE && (y2 - y1) >= MIN_SIZE) {
                int cls = c - 1;
                int pos = atomicAdd(&d_cnt2[cls][bkt], 1);
                if (pos < BCAP) {
                    d_cand_box[cls][bkt][pos] = make_float4(x1, y1, x2, y2);
                    d_cand_sg[cls][bkt][pos]  = make_float2(ev[j] * inv, __int_as_float(warp));
                }
            }
        }
    }
}

// ---------------- kernel 2: chunked NMS (16-wide tiles) + fused output, grid padded ----------------
__global__ __launch_bounds__(NMS_THREADS) void nms_out_kernel(
    const float* __restrict__ logit,
    const float* __restrict__ breg,
    const float* __restrict__ treg,
    const float* __restrict__ prop,
    const int* __restrict__ p_ih,
    const int* __restrict__ p_iw,
    float* __restrict__ out,
    int N, int C, int T, int M, int KC)
{
    int cls = blockIdx.x;
    if (cls >= KC) return;          // grid padded to >=148 to defeat low-grid throttle
    int tid = threadIdx.x;
    int laneId = tid & 31;
    int warpId = tid >> 5;

    __shared__ int    s_off[NBKT + 1];
    __shared__ unsigned long long s_key[CAP];
    __shared__ int    hist[NBINS];
    __shared__ unsigned long long s_sel[SELCAP];
    __shared__ float4 s_rbox[SELCAP];
    __shared__ float  s_rarea[SELCAP];
    __shared__ float4 a_box[NUM_DET];
    __shared__ float  a_area[NUM_DET];
    __shared__ int    a_gi[NUM_DET];
    __shared__ float  a_sc[NUM_DET];
    __shared__ int    s_cut, s_chunkn, s_nacc, s_selcnt;
    __shared__ int    s_pairm[2][16];

    // ---- bucket prefix (warp 0) ----
    if (warpId == 0) {
        int c0 = min(d_cnt2[cls][2 * laneId],     BCAP);
        int c1 = min(d_cnt2[cls][2 * laneId + 1], BCAP);
        int pair = c0 + c1;
        int incl = pair;
#pragma unroll
        for (int o = 1; o < 32; o <<= 1) {
            int v = __shfl_up_sync(0xFFFFFFFFu, incl, o);
            if (laneId >= o) incl += v;
        }
        s_off[2 * laneId]     = incl - pair;
        s_off[2 * laneId + 1] = incl - c1;
        if (laneId == 31) s_off[NBKT] = incl;
    }
    for (int i = tid; i < NBINS; i += NMS_THREADS) hist[i] = 0;
    if (tid == 0) s_nacc = 0;
    __syncthreads();

    if (tid < NBKT) d_cnt2[cls][tid] = 0;
    int cnt = s_off[NBKT];
    if (cnt > CAP) cnt = CAP;

    // ---- bucket-direct key load + histogram ----
    for (int b = warpId; b < NBKT; b += (NMS_THREADS >> 5)) {
        int off = s_off[b];
        int c   = s_off[b + 1] - off;
        for (int e = laneId; e < c; e += 32) {
            int i = off + e;
            if (i >= CAP) break;
            float2 sg = d_cand_sg[cls][b][e];
            unsigned u = __float_as_uint(sg.x);
            unsigned gi_inv = 0xFFFFu - (unsigned)__float_as_int(sg.y);
            s_key[i] = ((unsigned long long)u << 32) |
                       ((unsigned long long)gi_inv << 16) |
                       (unsigned long long)(unsigned)((b << 8) | e);
            int bin = min((int)(u >> 16) - HBASE, NBINS - 1);
            atomicAdd(&hist[bin], 1);
        }
    }
    __syncthreads();

    // ---- incremental descending-score chunks ----
    float4 rb[4];
    float  ra[4];
#pragma unroll
    for (int s = 0; s < 4; s++) { rb[s] = make_float4(0,0,0,0); ra[s] = 0.0f; }
    int naccr = 0;

    int hi_cut = NBINS;
    bool fb = false;

    while (naccr < NUM_DET && hi_cut > 0 && !fb) {
        if (warpId == 0) {
            int acc = 0, cut = 0, chn = 0;
            bool found = false;
            int baseStart = ((hi_cut - 1) >> 5) << 5;
            for (int base = baseStart; base >= 0; base -= 32) {
                int bin = base + laneId;
                int v = (bin < hi_cut) ? hist[bin] : 0;
                int tot = v;
#pragma unroll
                for (int o = 16; o; o >>= 1) tot += __shfl_xor_sync(0xFFFFFFFFu, tot, o);
                if (acc + tot >= CHUNK_TARGET) {
                    int suf = v;
#pragma unroll
                    for (int o = 1; o < 32; o <<= 1) {
                        int t = __shfl_down_sync(0xFFFFFFFFu, suf, o);
                        if (laneId + o < 32) suf += t;
                    }
                    unsigned bal = __ballot_sync(0xFFFFFFFFu, acc + suf >= CHUNK_TARGET);
                    int L = 31 - __clz(bal);
                    cut = base + L;
                    chn = acc + __shfl_sync(0xFFFFFFFFu, suf, L);
                    found = true;
                    break;
                }
                acc += tot;
            }
            if (!found) { cut = 0; chn = acc; }
            if (laneId == 0) { s_cut = cut; s_chunkn = chn; s_selcnt = 0; }
        }
        __syncthreads();
        int cutv = s_cut;
        int chn  = s_chunkn;

        if (chn > SELCAP) { fb = true; break; }

        if (chn > 0) {
            for (int i = tid; i < cnt; i += NMS_THREADS) {
                unsigned long long k = s_key[i];
                int bin = min((int)((unsigned)(k >> 32) >> 16) - HBASE, NBINS - 1);
                if (bin >= cutv && bin < hi_cut) {
                    int pos = atomicAdd(&s_selcnt, 1);
                    s_sel[pos] = k;
                }
            }
            __syncthreads();

            if (chn <= NMS_THREADS) {
                // register bitonic 256, descending
                unsigned long long kr = (tid < chn) ? s_sel[tid] : 0ull;
#pragma unroll
                for (int k = 2; k <= NMS_THREADS; k <<= 1) {
#pragma unroll
                    for (int j = k >> 1; j > 0; j >>= 1) {
                        unsigned long long o;
                        if (j >= 32) {
                            s_sel[tid] = kr;
                            __syncthreads();
                            o = s_sel[tid ^ j];
                            __syncthreads();
                        } else {
                            o = __shfl_xor_sync(0xFFFFFFFFu, kr, j);
                        }
                        bool keepMax = ((tid & k) == 0) == ((tid & j) == 0);
                        kr = keepMax ? u64max(kr, o) : u64min(kr, o);
                    }
                }
                s_sel[tid] = kr;
                __syncthreads();
            } else {
                for (int i = chn + tid; i < SELCAP; i += NMS_THREADS) s_sel[i] = 0ull;
                __syncthreads();
                for (int k = 2; k <= SELCAP; k <<= 1) {
                    for (int j = k >> 1; j > 0; j >>= 1) {
                        for (int idx = tid; idx < SELCAP; idx += NMS_THREADS) {
                            int l = idx ^ j;
                            if (l > idx) {
                                unsigned long long a = s_sel[idx];
                                unsigned long long b = s_sel[l];
                                bool up = ((idx & k) == 0);
                                if (up ? (a < b) : (a > b)) { s_sel[idx] = b; s_sel[l] = a; }
                            }
                        }
                        __syncthreads();
                    }
                }
            }

            for (int r = tid; r < chn; r += NMS_THREADS) {
                int slot = (int)(s_sel[r] & 0xFFFFu);
                float4 bx = d_cand_box[cls][slot >> 8][slot & 255];
                s_rbox[r]  = bx;
                s_rarea[r] = (bx.z - bx.x) * (bx.w - bx.y);
            }
            __syncthreads();

            // -- 16-wide single-barrier tiles --
            for (int tb = 0; tb < chn && naccr < NUM_DET; tb += 16) {
                int buf = (tb >> 4) & 1;
                int i1 = tb + warpId;
                int i2 = tb + 8 + warpId;

                bool sup1 = false, pair1 = false;
                bool sup2 = false, pair2 = false;
                if (i1 < chn) {
                    float4 b1 = s_rbox[i1];
                    float ca1 = s_rarea[i1];
#pragma unroll
                    for (int s = 0; s < 4; s++) {
                        int j = s * 32 + laneId;
                        if (j < naccr && iou_over(rb[s], ra[s], b1, ca1)) sup1 = true;
                    }
                    if (laneId < warpId)
                        pair1 = iou_over(s_rbox[tb + laneId], s_rarea[tb + laneId], b1, ca1);
                }
                if (i2 < chn) {
                    float4 b2 = s_rbox[i2];
                    float ca2 = s_rarea[i2];
#pragma unroll
                    for (int s = 0; s < 4; s++) {
                        int j = s * 32 + laneId;
                        if (j < naccr && iou_over(rb[s], ra[s], b2, ca2)) sup2 = true;
                    }
                    if (laneId < 8 + warpId)
                        pair2 = iou_over(s_rbox[tb + laneId], s_rarea[tb + laneId], b2, ca2);
                }
                unsigned bal1 = __ballot_sync(0xFFFFFFFFu, pair1) & ((1u << warpId) - 1u);
                unsigned bal2 = __ballot_sync(0xFFFFFFFFu, pair2) & ((1u << (8 + warpId)) - 1u);
                bool sa1 = __any_sync(0xFFFFFFFFu, sup1);
                bool sa2 = __any_sync(0xFFFFFFFFu, sup2);
                if (laneId == 0) {
                    s_pairm[buf][warpId]     = (int)bal1 | (sa1 ? 0x10000 : 0);
                    s_pairm[buf][8 + warpId] = (int)bal2 | (sa2 ? 0x10000 : 0);
                }
                __syncthreads();

                int kept = 0, newn = 0;
#pragma unroll
                for (int t = 0; t < 16; t++) {
                    if (tb + t < chn && naccr + newn < NUM_DET) {
                        int pmv = s_pairm[buf][t];
                        if (!(pmv & 0x10000) && !(pmv & kept)) { kept |= 1 << t; newn++; }
                    }
                }

                if (warpId == 0 && laneId < 16 && ((kept >> laneId) & 1)) {
                    int pos = naccr + __popc(kept & ((1 << laneId) - 1));
                    int ii = tb + laneId;
                    unsigned long long k = s_sel[ii];
                    a_box[pos]  = s_rbox[ii];
                    a_area[pos] = s_rarea[ii];
                    a_gi[pos]   = (int)(0xFFFFu - ((unsigned)(k >> 16) & 0xFFFFu));
                    a_sc[pos]   = __uint_as_float((unsigned)(k >> 32));
                }

                int rank = 0;
#pragma unroll
                for (int t = 0; t < 16; t++) {
                    if ((kept >> t) & 1) {
                        int pos = naccr + rank;
                        if ((pos & 31) == laneId) {
                            int sl = pos >> 5;
                            float4 bb = s_rbox[tb + t];
                            float  aa = s_rarea[tb + t];
#pragma unroll
                            for (int q = 0; q < 4; q++) if (q == sl) { rb[q] = bb; ra[q] = aa; }
                        }
                        rank++;
                    }
                }
                naccr += newn;
            }
            if (tid == 0) s_nacc = naccr;
            __syncthreads();
        }

        hi_cut = cutv;
        __syncthreads();
    }

    if (fb) {
        // ---- compact exact fallback (never expected): serial argmax greedy, warp 0 ----
        if (tid == 0) s_nacc = 0;
        __syncthreads();
        if (warpId == 0) {
            int nacc = 0;
            while (nacc < NUM_DET) {
                unsigned long long bk = 0ull;
                for (int i = laneId; i < cnt; i += 32) bk = u64max(bk, s_key[i]);
#pragma unroll
                for (int o = 16; o; o >>= 1)
                    bk = u64max(bk, __shfl_down_sync(0xFFFFFFFFu, bk, o));
                bk = __shfl_sync(0xFFFFFFFFu, bk, 0);
                if (bk == 0ull) break;
                int slot = (int)(bk & 0xFFFFu);
                float4 b = d_cand_box[cls][slot >> 8][slot & 255];
                float carea = (b.z - b.x) * (b.w - b.y);
                if (laneId == 0) {
                    a_box[nacc]  = b;
                    a_area[nacc] = carea;
                    a_gi[nacc]   = (int)(0xFFFFu - ((unsigned)(bk >> 16) & 0xFFFFu));
                    a_sc[nacc]   = __uint_as_float((unsigned)(bk >> 32));
                }
                __syncwarp();
                for (int i = laneId; i < cnt; i += 32) {
                    unsigned long long k = s_key[i];
                    if (k != 0ull) {
                        int sl = (int)(k & 0xFFFFu);
                        float4 bb = d_cand_box[cls][sl >> 8][sl & 255];
                        float aa = (bb.z - bb.x) * (bb.w - bb.y);
                        if (iou_over(b, carea, bb, aa)) s_key[i] = 0ull;
                    }
                }
                nacc++;
                __syncwarp();
            }
            if (laneId == 0) s_nacc = nacc;
        }
        __syncthreads();
    }
    __syncthreads();
    int ndet = s_nacc;

    // ---- fused output ----
    float W = (float)(*p_iw);
    float H = (float)(*p_ih);
    int clabel = cls + 1;

    size_t OFF_LBL = (size_t)M * 4;
    size_t OFF_SC  = OFF_LBL + M;
    size_t OFF_FUT = OFF_SC + M;
    size_t OFF_VAL = OFF_FUT + (size_t)T * M * 4;

    for (int d = tid; d < NUM_DET; d += NMS_THREADS) {
        bool v = (d < ndet);
        int g = v ? a_gi[d] : 0;
        int m = cls * NUM_DET + d;

        float4 p = ((const float4*)prop)[g];
        const float4 td0 = *(const float4*)(treg + (((size_t)0 * N + g) * C + clabel) * 4);
        const float4 td1 = *(const float4*)(treg + (((size_t)1 * N + g) * C + clabel) * 4);
        const float4 td2 = *(const float4*)(treg + (((size_t)2 * N + g) * C + clabel) * 4);

        float4 obox;
        float scv;
        if (v) {
            obox = a_box[d];
            scv  = a_sc[d];
        } else {
            float lg  = logit[clabel];
            scv = expf(lg - d_row_max0) / d_row_den0;
            const float4 dd = *(const float4*)(breg + (size_t)clabel * 4);
            float x1, y1, x2, y2;
            decode_box(dd.x, dd.y, dd.z, dd.w, p.x, p.y, p.z, p.w, x1, y1, x2, y2);
            obox = make_float4(clipf(x1, W), clipf(y1, H), clipf(x2, W), clipf(y2, H));
        }

        ((float4*)out)[m] = obox;
        out[OFF_LBL + m] = (float)clabel;
        out[OFF_SC + m]  = scv;
        out[OFF_VAL + m] = v ? 1.0f : 0.0f;

        float cx1 = p.x, cy1 = p.y, cx2 = p.z, cy2 = p.w;
        float4 tds[3] = {td0, td1, td2};
#pragma unroll
        for (int t = 0; t < 3; t++) {
            float nx1, ny1, nx2, ny2;
            decode_box(tds[t].x, tds[t].y, tds[t].z, tds[t].w,
                       cx1, cy1, cx2, cy2, nx1, ny1, nx2, ny2);
            float4 of = make_float4(clipf(nx1, W), clipf(ny1, H), clipf(nx2, W), clipf(ny2, H));
            ((float4*)(out + OFF_FUT))[(size_t)t * M + m] = of;
            cx1 = nx1; cy1 = ny1; cx2 = nx2; cy2 = ny2;
        }
    }
}

// ---------------- launch ----------------
extern "C" void kernel_launch(void* const* d_in, const int* in_sizes, int n_in,
                              void* d_out, int out_size)
{
    const float* logit = (const float*)d_in[0];
    const float* breg  = (const float*)d_in[1];
    const float* treg  = (const float*)d_in[2];
    const float* prop  = (const float*)d_in[3];
    const int*   p_ih  = (const int*)d_in[4];
    const int*   p_iw  = (const int*)d_in[5];

    int N = in_sizes[3] / 4;
    int C = in_sizes[0] / N;
    int T = in_sizes[2] / in_sizes[1];
    int KC = C - 1;
    int M = KC * NUM_DET;

    int warpsPerBlock = 8;
    int blocks = (N + warpsPerBlock - 1) / warpsPerBlock;
    if (C == 91) {
        score_extract_t<91><<<blocks, 256>>>(logit, breg, prop, p_ih, p_iw, N, C);
    } else {
        score_extract_t<0><<<blocks, 256>>>(logit, breg, prop, p_ih, p_iw, N, C);
    }

    int nmsGrid = (KC < MIN_GRID) ? MIN_GRID : KC;
    nms_out_kernel<<<nmsGrid, NMS_THREADS>>>(logit, breg, treg, prop, p_ih, p_iw,
                                             (float*)d_out, N, C, T, M, KC);
}

// round 13
// speedup vs baseline: 1.1399x; 1.0685x over previous
#include <cuda_runtime.h>
#include <math.h>
#include <stdint.h>

#define KCMAX 95
#define NUM_DET 100
#define SCORE_THRESH 0.05f
#define NMS_THRESH 0.5f
#define MIN_SIZE 1.0f
#define BBOX_CLIP 4.135166556742356f
#define NMS_THREADS 256
#define CAP 2048
#define NBKT 64
#define BCAP 256
#define NBINS 576
#define HBASE 0x3D4C             // bits(0.05f) >> 16
#define CHUNK_TARGET 224
#define SELCAP 512
#define MIN_GRID 148

// ---------------- device scratch ----------------
__device__ float  d_row_max0;
__device__ float  d_row_den0;
__device__ int    d_cnt2[KCMAX][NBKT];
__device__ int    d_hist[KCMAX][NBINS];           // built by extract, reset by nms
__device__ float4 d_cand_box[KCMAX][NBKT][BCAP];
__device__ unsigned long long d_cand_key[KCMAX][NBKT][BCAP];

// ---------------- helpers ----------------
__device__ __forceinline__ void decode_box(
    float d0, float d1, float d2, float d3,
    float bx1, float by1, float bx2, float by2,
    float& ox1, float& oy1, float& ox2, float& oy2)
{
    float w  = bx2 - bx1;
    float h  = by2 - by1;
    float cx = bx1 + 0.5f * w;
    float cy = by1 + 0.5f * h;
    float dx = d0 / 10.0f;
    float dy = d1 / 10.0f;
    float dw = fminf(d2 / 5.0f, BBOX_CLIP);
    float dh = fminf(d3 / 5.0f, BBOX_CLIP);
    float pcx = dx * w + cx;
    float pcy = dy * h + cy;
    float pw  = expf(dw) * w;
    float ph  = expf(dh) * h;
    ox1 = pcx - 0.5f * pw;
    oy1 = pcy - 0.5f * ph;
    ox2 = pcx + 0.5f * pw;
    oy2 = pcy + 0.5f * ph;
}

__device__ __forceinline__ float clipf(float v, float hi) {
    return fminf(fmaxf(v, 0.0f), hi);
}

// exact: when inter == 0, iou = 0/positive = 0 -> never > 0.5; skip the divide.
__device__ __forceinline__ bool iou_over(const float4& a, float aarea,
                                         const float4& b, float barea)
{
    float ix1 = fmaxf(a.x, b.x);
    float iy1 = fmaxf(a.y, b.y);
    float ix2 = fminf(a.z, b.z);
    float iy2 = fminf(a.w, b.w);
    float iw = fmaxf(0.0f, ix2 - ix1);
    float ih = fmaxf(0.0f, iy2 - iy1);
    float inter = iw * ih;
    if (inter <= 0.0f) return false;
    float iou = inter / (aarea + barea - inter + 1e-9f);
    return iou > NMS_THRESH;
}

__device__ __forceinline__ unsigned long long u64max(unsigned long long a, unsigned long long b) { return a > b ? a : b; }
__device__ __forceinline__ unsigned long long u64min(unsigned long long a, unsigned long long b) { return a < b ? a : b; }

// ---------------- kernel 1: softmax + decode + filter + compact + key/hist ----------------
template <int CT>
__global__ __launch_bounds__(256) void score_extract_t(
    const float* __restrict__ logit,
    const float* __restrict__ breg,
    const float* __restrict__ prop,
    const int* __restrict__ p_ih,
    const int* __restrict__ p_iw,
    int N, int Crt)
{
    const int C = (CT > 0) ? CT : Crt;
    int warp = (blockIdx.x * blockDim.x + threadIdx.x) >> 5;
    int lane = threadIdx.x & 31;
    if (warp >= N) return;

    const float* row = logit + (size_t)warp * C;

    float lv[3];
    float mx = -INFINITY;
#pragma unroll
    for (int j = 0; j < 3; j++) {
        int c = lane + 32 * j;
        lv[j] = (c < C) ? row[c] : -INFINITY;
        mx = fmaxf(mx, lv[j]);
    }
#pragma unroll
    for (int o = 16; o; o >>= 1) mx = fmaxf(mx, __shfl_xor_sync(0xFFFFFFFFu, mx, o));

    float ev[3];
    float s = 0.0f;
#pragma unroll
    for (int j = 0; j < 3; j++) {
        int c = lane + 32 * j;
        ev[j] = (c < C) ? expf(lv[j] - mx) : 0.0f;
        s += ev[j];
    }
#pragma unroll
    for (int o = 16; o; o >>= 1) s += __shfl_xor_sync(0xFFFFFFFFu, s, o);

    if (warp == 0 && lane == 0) { d_row_max0 = mx; d_row_den0 = s; }
    float inv = 1.0f / s;

    unsigned pm = 0;
#pragma unroll
    for (int j = 0; j < 3; j++) {
        int c = lane + 32 * j;
        if (c > 0 && c < C && ev[j] * inv >= SCORE_THRESH) pm |= 1u << j;
    }

    if (pm) {
        float W = (float)(*p_iw);
        float H = (float)(*p_ih);
        float4 p = ((const float4*)prop)[warp];
        int bkt = blockIdx.x & (NBKT - 1);
#pragma unroll
        for (int j = 0; j < 3; j++) {
            if (!(pm & (1u << j))) continue;
            int c = lane + 32 * j;
            const float4 dd = *(const float4*)(breg + ((size_t)warp * C + c) * 4);
            float x1, y1, x2, y2;
            decode_box(dd.x, dd.y, dd.z, dd.w, p.x, p.y, p.z, p.w, x1, y1, x2, y2);
            x1 = clipf(x1, W); x2 = clipf(x2, W);
            y1 = clipf(y1, H); y2 = clipf(y2, H);
            if ((x2 - x1) >= MIN_SIZE && (y2 - y1) >= MIN_SIZE) {
                int cls = c - 1;
                int pos = atomicAdd(&d_cnt2[cls][bkt], 1);
                if (pos < BCAP) {
                    float pscore = ev[j] * inv;
                    unsigned u = __float_as_uint(pscore);         // score > 0
                    unsigned gi_inv = 0xFFFFu - (unsigned)warp;   // N < 65536
                    d_cand_box[cls][bkt][pos] = make_float4(x1, y1, x2, y2);
                    d_cand_key[cls][bkt][pos] =
                        ((unsigned long long)u << 32) |
                        ((unsigned long long)gi_inv << 16) |
                        (unsigned long long)(unsigned)((bkt << 8) | pos);
                    int bin = min((int)(u >> 16) - HBASE, NBINS - 1);
                    atomicAdd(&d_hist[cls][bin], 1);
                }
            }
        }
    }
}

// ---------------- kernel 2: chunked NMS (16-wide tiles) + fused output ----------------
__global__ __launch_bounds__(NMS_THREADS) void nms_out_kernel(
    const float* __restrict__ logit,
    const float* __restrict__ breg,
    const float* __restrict__ treg,
    const float* __restrict__ prop,
    const int* __restrict__ p_ih,
    const int* __restrict__ p_iw,
    float* __restrict__ out,
    int N, int C, int T, int M, int KC)
{
    int cls = blockIdx.x;
    if (cls >= KC) return;
    int tid = threadIdx.x;
    int laneId = tid & 31;
    int warpId = tid >> 5;

    __shared__ int    s_off[NBKT + 1];
    __shared__ unsigned long long s_key[CAP];
    __shared__ int    s_hist[NBINS];
    __shared__ unsigned long long s_sel[SELCAP];
    __shared__ float4 s_rbox[SELCAP];
    __shared__ float  s_rarea[SELCAP];
    __shared__ float4 a_box[NUM_DET];
    __shared__ float  a_area[NUM_DET];
    __shared__ int    a_gi[NUM_DET];
    __shared__ float  a_sc[NUM_DET];
    __shared__ int    s_cut, s_chunkn, s_nacc, s_selcnt;
    __shared__ int    s_pairm[2][16];

    // ---- bucket prefix (warp 0) ----
    if (warpId == 0) {
        int c0 = min(d_cnt2[cls][2 * laneId],     BCAP);
        int c1 = min(d_cnt2[cls][2 * laneId + 1], BCAP);
        int pair = c0 + c1;
        int incl = pair;
#pragma unroll
        for (int o = 1; o < 32; o <<= 1) {
            int v = __shfl_up_sync(0xFFFFFFFFu, incl, o);
            if (laneId >= o) incl += v;
        }
        s_off[2 * laneId]     = incl - pair;
        s_off[2 * laneId + 1] = incl - c1;
        if (laneId == 31) s_off[NBKT] = incl;
    }
    // hist: global -> shared copy, then reset global for next replay
    for (int i = tid; i < NBINS; i += NMS_THREADS) {
        s_hist[i] = d_hist[cls][i];
        d_hist[cls][i] = 0;
    }
    if (tid == 0) s_nacc = 0;
    __syncthreads();

    if (tid < NBKT) d_cnt2[cls][tid] = 0;
    int cnt = s_off[NBKT];
    if (cnt > CAP) cnt = CAP;

    // ---- flat MLP key load: batch binary searches, then batch global loads ----
    {
        int idxs[8];
        unsigned long long kk[8];
#pragma unroll
        for (int r = 0; r < 8; r++) {
            int i = r * NMS_THREADS + tid;
            idxs[r] = -1;
            if (i < cnt) {
                int lo = 0, hi = NBKT;
#pragma unroll
                for (int b = 0; b < 6; b++) {
                    int mid = (lo + hi) >> 1;
                    if (s_off[mid] <= i) lo = mid; else hi = mid;
                }
                idxs[r] = (lo << 8) | (i - s_off[lo]);
            }
        }
#pragma unroll
        for (int r = 0; r < 8; r++)
            if (idxs[r] >= 0) kk[r] = d_cand_key[cls][idxs[r] >> 8][idxs[r] & 255];
#pragma unroll
        for (int r = 0; r < 8; r++)
            if (idxs[r] >= 0) s_key[r * NMS_THREADS + tid] = kk[r];
    }
    __syncthreads();

    // ---- incremental descending-score chunks ----
    float4 rb[4];
    float  ra[4];
#pragma unroll
    for (int s = 0; s < 4; s++) { rb[s] = make_float4(0,0,0,0); ra[s] = 0.0f; }
    int naccr = 0;

    int hi_cut = NBINS;
    bool fb = false;

    while (naccr < NUM_DET && hi_cut > 0 && !fb) {
        if (warpId == 0) {
            int acc = 0, cut = 0, chn = 0;
            bool found = false;
            int baseStart = ((hi_cut - 1) >> 5) << 5;
            for (int base = baseStart; base >= 0; base -= 32) {
                int bin = base + laneId;
                int v = (bin < hi_cut) ? s_hist[bin] : 0;
                int tot = v;
#pragma unroll
                for (int o = 16; o; o >>= 1) tot += __shfl_xor_sync(0xFFFFFFFFu, tot, o);
                if (acc + tot >= CHUNK_TARGET) {
                    int suf = v;
#pragma unroll
                    for (int o = 1; o < 32; o <<= 1) {
                        int t = __shfl_down_sync(0xFFFFFFFFu, suf, o);
                        if (laneId + o < 32) suf += t;
                    }
                    unsigned bal = __ballot_sync(0xFFFFFFFFu, acc + suf >= CHUNK_TARGET);
                    int L = 31 - __clz(bal);
                    cut = base + L;
                    chn = acc + __shfl_sync(0xFFFFFFFFu, suf, L);
                    found = true;
                    break;
                }
                acc += tot;
            }
            if (!found) { cut = 0; chn = acc; }
            if (laneId == 0) { s_cut = cut; s_chunkn = chn; s_selcnt = 0; }
        }
        __syncthreads();
        int cutv = s_cut;
        int chn  = s_chunkn;

        if (chn > SELCAP) { fb = true; break; }

        if (chn > 0) {
            for (int i = tid; i < cnt; i += NMS_THREADS) {
                unsigned long long k = s_key[i];
                int bin = min((int)((unsigned)(k >> 32) >> 16) - HBASE, NBINS - 1);
                if (bin >= cutv && bin < hi_cut) {
                    int pos = atomicAdd(&s_selcnt, 1);
                    s_sel[pos] = k;
                }
            }
            __syncthreads();
            chn = min(chn, s_selcnt);    // guard vs clamped cnt

            if (chn <= NMS_THREADS) {
                unsigned long long kr = (tid < chn) ? s_sel[tid] : 0ull;
#pragma unroll
                for (int k = 2; k <= NMS_THREADS; k <<= 1) {
#pragma unroll
                    for (int j = k >> 1; j > 0; j >>= 1) {
                        unsigned long long o;
                        if (j >= 32) {
                            s_sel[tid] = kr;
                            __syncthreads();
                            o = s_sel[tid ^ j];
                            __syncthreads();
                        } else {
                            o = __shfl_xor_sync(0xFFFFFFFFu, kr, j);
                        }
                        bool keepMax = ((tid & k) == 0) == ((tid & j) == 0);
                        kr = keepMax ? u64max(kr, o) : u64min(kr, o);
                    }
                }
                s_sel[tid] = kr;
                __syncthreads();
            } else {
                for (int i = chn + tid; i < SELCAP; i += NMS_THREADS) s_sel[i] = 0ull;
                __syncthreads();
                for (int k = 2; k <= SELCAP; k <<= 1) {
                    for (int j = k >> 1; j > 0; j >>= 1) {
                        for (int idx = tid; idx < SELCAP; idx += NMS_THREADS) {
                            int l = idx ^ j;
                            if (l > idx) {
                                unsigned long long a = s_sel[idx];
                                unsigned long long b = s_sel[l];
                                bool up = ((idx & k) == 0);
                                if (up ? (a < b) : (a > b)) { s_sel[idx] = b; s_sel[l] = a; }
                            }
                        }
                        __syncthreads();
                    }
                }
            }

            for (int r = tid; r < chn; r += NMS_THREADS) {
                int slot = (int)(s_sel[r] & 0xFFFFu);
                float4 bx = d_cand_box[cls][slot >> 8][slot & 255];
                s_rbox[r]  = bx;
                s_rarea[r] = (bx.z - bx.x) * (bx.w - bx.y);
            }
            __syncthreads();

            // -- 16-wide single-barrier tiles --
            for (int tb = 0; tb < chn && naccr < NUM_DET; tb += 16) {
                int buf = (tb >> 4) & 1;
                int i1 = tb + warpId;
                int i2 = tb + 8 + warpId;

                bool sup1 = false, pair1 = false;
                bool sup2 = false, pair2 = false;
                if (i1 < chn) {
                    float4 b1 = s_rbox[i1];
                    float ca1 = s_rarea[i1];
#pragma unroll
                    for (int s = 0; s < 4; s++) {
                        int j = s * 32 + laneId;
                        if (j < naccr && iou_over(rb[s], ra[s], b1, ca1)) sup1 = true;
                    }
                    if (laneId < warpId)
                        pair1 = iou_over(s_rbox[tb + laneId], s_rarea[tb + laneId], b1, ca1);
                }
                if (i2 < chn) {
                    float4 b2 = s_rbox[i2];
                    float ca2 = s_rarea[i2];
#pragma unroll
                    for (int s = 0; s < 4; s++) {
                        int j = s * 32 + laneId;
                        if (j < naccr && iou_over(rb[s], ra[s], b2, ca2)) sup2 = true;
                    }
                    if (laneId < 8 + warpId)
                        pair2 = iou_over(s_rbox[tb + laneId], s_rarea[tb + laneId], b2, ca2);
                }
                unsigned bal1 = __ballot_sync(0xFFFFFFFFu, pair1) & ((1u << warpId) - 1u);
                unsigned bal2 = __ballot_sync(0xFFFFFFFFu, pair2) & ((1u << (8 + warpId)) - 1u);
                bool sa1 = __any_sync(0xFFFFFFFFu, sup1);
                bool sa2 = __any_sync(0xFFFFFFFFu, sup2);
                if (laneId == 0) {
                    s_pairm[buf][warpId]     = (int)bal1 | (sa1 ? 0x10000 : 0);
                    s_pairm[buf][8 + warpId] = (int)bal2 | (sa2 ? 0x10000 : 0);
                }
                __syncthreads();

                int kept = 0, newn = 0;
#pragma unroll
                for (int t = 0; t < 16; t++) {
                    if (tb + t < chn && naccr + newn < NUM_DET) {
                        int pmv = s_pairm[buf][t];
                        if (!(pmv & 0x10000) && !(pmv & kept)) { kept |= 1 << t; newn++; }
                    }
                }

                if (warpId == 0 && laneId < 16 && ((kept >> laneId) & 1)) {
                    int pos = naccr + __popc(kept & ((1 << laneId) - 1));
                    int ii = tb + laneId;
                    unsigned long long k = s_sel[ii];
                    a_box[pos]  = s_rbox[ii];
                    a_area[pos] = s_rarea[ii];
                    a_gi[pos]   = (int)(0xFFFFu - ((unsigned)(k >> 16) & 0xFFFFu));
                    a_sc[pos]   = __uint_as_float((unsigned)(k >> 32));
                }

                int rank = 0;
#pragma unroll
                for (int t = 0; t < 16; t++) {
                    if ((kept >> t) & 1) {
                        int pos = naccr + rank;
                        if ((pos & 31) == laneId) {
                            int sl = pos >> 5;
                            float4 bb = s_rbox[tb + t];
                            float  aa = s_rarea[tb + t];
#pragma unroll
                            for (int q = 0; q < 4; q++) if (q == sl) { rb[q] = bb; ra[q] = aa; }
                        }
                        rank++;
                    }
                }
                naccr += newn;
            }
            if (tid == 0) s_nacc = naccr;
            __syncthreads();
        }

        hi_cut = cutv;
        __syncthreads();
    }

    if (fb) {
        // compact exact fallback: serial argmax greedy (warp 0)
        if (tid == 0) s_nacc = 0;
        __syncthreads();
        if (warpId == 0) {
            int nacc = 0;
            while (nacc < NUM_DET) {
                unsigned long long bk = 0ull;
                for (int i = laneId; i < cnt; i += 32) bk = u64max(bk, s_key[i]);
#pragma unroll
                for (int o = 16; o; o >>= 1)
                    bk = u64max(bk, __shfl_down_sync(0xFFFFFFFFu, bk, o));
                bk = __shfl_sync(0xFFFFFFFFu, bk, 0);
                if (bk == 0ull) break;
                int slot = (int)(bk & 0xFFFFu);
                float4 b = d_cand_box[cls][slot >> 8][slot & 255];
                float carea = (b.z - b.x) * (b.w - b.y);
                if (laneId == 0) {
                    a_box[nacc]  = b;
                    a_area[nacc] = carea;
                    a_gi[nacc]   = (int)(0xFFFFu - ((unsigned)(bk >> 16) & 0xFFFFu));
                    a_sc[nacc]   = __uint_as_float((unsigned)(bk >> 32));
                }
                __syncwarp();
                for (int i = laneId; i < cnt; i += 32) {
                    unsigned long long k = s_key[i];
                    if (k != 0ull) {
                        int sl = (int)(k & 0xFFFFu);
                        float4 bb = d_cand_box[cls][sl >> 8][sl & 255];
                        float aa = (bb.z - bb.x) * (bb.w - bb.y);
                        if (iou_over(b, carea, bb, aa)) s_key[i] = 0ull;
                    }
                }
                nacc++;
                __syncwarp();
            }
            if (laneId == 0) s_nacc = nacc;
        }
        __syncthreads();
    }
    __syncthreads();
    int ndet = s_nacc;

    // ---- fused output ----
    float W = (float)(*p_iw);
    float H = (float)(*p_ih);
    int clabel = cls + 1;

    size_t OFF_LBL = (size_t)M * 4;
    size_t OFF_SC  = OFF_LBL + M;
    size_t OFF_FUT = OFF_SC + M;
    size_t OFF_VAL = OFF_FUT + (size_t)T * M * 4;

    for (int d = tid; d < NUM_DET; d += NMS_THREADS) {
        bool v = (d < ndet);
        int g = v ? a_gi[d] : 0;
        int m = cls * NUM_DET + d;

        float4 p = ((const float4*)prop)[g];
        const float4 td0 = *(const float4*)(treg + (((size_t)0 * N + g) * C + clabel) * 4);
        const float4 td1 = *(const float4*)(treg + (((size_t)1 * N + g) * C + clabel) * 4);
        const float4 td2 = *(const float4*)(treg + (((size_t)2 * N + g) * C + clabel) * 4);

        float4 obox;
        float scv;
        if (v) {
            obox = a_box[d];
            scv  = a_sc[d];
        } else {
            float lg  = logit[clabel];
            scv = expf(lg - d_row_max0) / d_row_den0;
            const float4 dd = *(const float4*)(breg + (size_t)clabel * 4);
            float x1, y1, x2, y2;
            decode_box(dd.x, dd.y, dd.z, dd.w, p.x, p.y, p.z, p.w, x1, y1, x2, y2);
            obox = make_float4(clipf(x1, W), clipf(y1, H), clipf(x2, W), clipf(y2, H));
        }

        ((float4*)out)[m] = obox;
        out[OFF_LBL + m] = (float)clabel;
        out[OFF_SC + m]  = scv;
        out[OFF_VAL + m] = v ? 1.0f : 0.0f;

        float cx1 = p.x, cy1 = p.y, cx2 = p.z, cy2 = p.w;
        float4 tds[3] = {td0, td1, td2};
#pragma unroll
        for (int t = 0; t < 3; t++) {
            float nx1, ny1, nx2, ny2;
            decode_box(tds[t].x, tds[t].y, tds[t].z, tds[t].w,
                       cx1, cy1, cx2, cy2, nx1, ny1, nx2, ny2);
            float4 of = make_float4(clipf(nx1, W), clipf(ny1, H), clipf(nx2, W), clipf(ny2, H));
            ((float4*)(out + OFF_FUT))[(size_t)t * M + m] = of;
            cx1 = nx1; cy1 = ny1; cx2 = nx2; cy2 = ny2;
        }
    }
}

// ---------------- launch ----------------
extern "C" void kernel_launch(void* const* d_in, const int* in_sizes, int n_in,
                              void* d_out, int out_size)
{
    const float* logit = (const float*)d_in[0];
    const float* breg  = (const float*)d_in[1];
    const float* treg  = (const float*)d_in[2];
    const float* prop  = (const float*)d_in[3];
    const int*   p_ih  = (const int*)d_in[4];
    const int*   p_iw  = (const int*)d_in[5];

    int N = in_sizes[3] / 4;
    int C = in_sizes[0] / N;
    int T = in_sizes[2] / in_sizes[1];
    int KC = C - 1;
    int M = KC * NUM_DET;

    int warpsPerBlock = 8;
    int blocks = (N + warpsPerBlock - 1) / warpsPerBlock;
    if (C == 91) {
        score_extract_t<91><<<blocks, 256>>>(logit, breg, prop, p_ih, p_iw, N, C);
    } else {
        score_extract_t<0><<<blocks, 256>>>(logit, breg, prop, p_ih, p_iw, N, C);
    }

    int nmsGrid = (KC < MIN_GRID) ? MIN_GRID : KC;
    nms_out_kernel<<<nmsGrid, NMS_THREADS>>>(logit, breg, treg, prop, p_ih, p_iw,
                                             (float*)d_out, N, C, T, M, KC);
}

// round 14
// speedup vs baseline: 1.3541x; 1.1879x over previous
#include <cuda_runtime.h>
#include <math.h>
#include <stdint.h>

#define KCMAX 95
#define NUM_DET 100
#define SCORE_THRESH 0.05f
#define NMS_THRESH 0.5f
#define MIN_SIZE 1.0f
#define BBOX_CLIP 4.135166556742356f
#define NMS_THREADS 256
#define CAP 2048
#define NBKT 64
#define BCAP 256
#define NBINS 576
#define HBASE 0x3D4C             // bits(0.05f) >> 16
#define CHUNK_TARGET 224
#define SELCAP 512
#define MIN_GRID 148

// ---------------- device scratch ----------------
__device__ float  d_row_max0;
__device__ float  d_row_den0;
__device__ int    d_cnt2[KCMAX][NBKT];
__device__ int    d_hist[KCMAX][NBINS];           // built by extract, reset by nms
__device__ float4 d_cand_box[KCMAX][NBKT][BCAP];
__device__ unsigned long long d_cand_key[KCMAX][NBKT][BCAP];

// ---------------- helpers ----------------
__device__ __forceinline__ void decode_box(
    float d0, float d1, float d2, float d3,
    float bx1, float by1, float bx2, float by2,
    float& ox1, float& oy1, float& ox2, float& oy2)
{
    float w  = bx2 - bx1;
    float h  = by2 - by1;
    float cx = bx1 + 0.5f * w;
    float cy = by1 + 0.5f * h;
    float dx = d0 / 10.0f;
    float dy = d1 / 10.0f;
    float dw = fminf(d2 / 5.0f, BBOX_CLIP);
    float dh = fminf(d3 / 5.0f, BBOX_CLIP);
    float pcx = dx * w + cx;
    float pcy = dy * h + cy;
    float pw  = expf(dw) * w;
    float ph  = expf(dh) * h;
    ox1 = pcx - 0.5f * pw;
    oy1 = pcy - 0.5f * ph;
    ox2 = pcx + 0.5f * pw;
    oy2 = pcy + 0.5f * ph;
}

__device__ __forceinline__ float clipf(float v, float hi) {
    return fminf(fmaxf(v, 0.0f), hi);
}

// exact: inter == 0 -> iou = 0 -> never > 0.5; skip the divide.
__device__ __forceinline__ bool iou_over(const float4& a, float aarea,
                                         const float4& b, float barea)
{
    float ix1 = fmaxf(a.x, b.x);
    float iy1 = fmaxf(a.y, b.y);
    float ix2 = fminf(a.z, b.z);
    float iy2 = fminf(a.w, b.w);
    float iw = fmaxf(0.0f, ix2 - ix1);
    float ih = fmaxf(0.0f, iy2 - iy1);
    float inter = iw * ih;
    if (inter <= 0.0f) return false;
    float iou = inter / (aarea + barea - inter + 1e-9f);
    return iou > NMS_THRESH;
}

__device__ __forceinline__ unsigned long long u64max(unsigned long long a, unsigned long long b) { return a > b ? a : b; }
__device__ __forceinline__ unsigned long long u64min(unsigned long long a, unsigned long long b) { return a < b ? a : b; }

// ---------------- kernel 1: softmax + decode + filter + compact + key/hist ----------------
template <int CT>
__global__ __launch_bounds__(256) void score_extract_t(
    const float* __restrict__ logit,
    const float* __restrict__ breg,
    const float* __restrict__ prop,
    const int* __restrict__ p_ih,
    const int* __restrict__ p_iw,
    int N, int Crt)
{
    const int C = (CT > 0) ? CT : Crt;
    int warp = (blockIdx.x * blockDim.x + threadIdx.x) >> 5;
    int lane = threadIdx.x & 31;
    if (warp >= N) return;

    const float* row = logit + (size_t)warp * C;

    float lv[3];
    float mx = -INFINITY;
#pragma unroll
    for (int j = 0; j < 3; j++) {
        int c = lane + 32 * j;
        lv[j] = (c < C) ? row[c] : -INFINITY;
        mx = fmaxf(mx, lv[j]);
    }
#pragma unroll
    for (int o = 16; o; o >>= 1) mx = fmaxf(mx, __shfl_xor_sync(0xFFFFFFFFu, mx, o));

    float ev[3];
    float s = 0.0f;
#pragma unroll
    for (int j = 0; j < 3; j++) {
        int c = lane + 32 * j;
        ev[j] = (c < C) ? expf(lv[j] - mx) : 0.0f;
        s += ev[j];
    }
#pragma unroll
    for (int o = 16; o; o >>= 1) s += __shfl_xor_sync(0xFFFFFFFFu, s, o);

    if (warp == 0 && lane == 0) { d_row_max0 = mx; d_row_den0 = s; }
    float inv = 1.0f / s;

    unsigned pm = 0;
#pragma unroll
    for (int j = 0; j < 3; j++) {
        int c = lane + 32 * j;
        if (c > 0 && c < C && ev[j] * inv >= SCORE_THRESH) pm |= 1u << j;
    }

    if (pm) {
        float W = (float)(*p_iw);
        float H = (float)(*p_ih);
        float4 p = ((const float4*)prop)[warp];
        int bkt = blockIdx.x & (NBKT - 1);
#pragma unroll
        for (int j = 0; j < 3; j++) {
            if (!(pm & (1u << j))) continue;
            int c = lane + 32 * j;
            const float4 dd = *(const float4*)(breg + ((size_t)warp * C + c) * 4);
            float x1, y1, x2, y2;
            decode_box(dd.x, dd.y, dd.z, dd.w, p.x, p.y, p.z, p.w, x1, y1, x2, y2);
            x1 = clipf(x1, W); x2 = clipf(x2, W);
            y1 = clipf(y1, H); y2 = clipf(y2, H);
            if ((x2 - x1) >= MIN_SIZE && (y2 - y1) >= MIN_SIZE) {
                int cls = c - 1;
                int pos = atomicAdd(&d_cnt2[cls][bkt], 1);
                if (pos < BCAP) {
                    float pscore = ev[j] * inv;
                    unsigned u = __float_as_uint(pscore);         // score > 0
                    unsigned gi_inv = 0xFFFFu - (unsigned)warp;   // N < 65536
                    d_cand_box[cls][bkt][pos] = make_float4(x1, y1, x2, y2);
                    d_cand_key[cls][bkt][pos] =
                        ((unsigned long long)u << 32) |
                        ((unsigned long long)gi_inv << 16) |
                        (unsigned long long)(unsigned)((bkt << 8) | pos);
                    int bin = min((int)(u >> 16) - HBASE, NBINS - 1);
                    atomicAdd(&d_hist[cls][bin], 1);
                }
            }
        }
    }
}

// ---------------- kernel 2: chunked NMS (16-wide tiles) + fused output ----------------
__global__ __launch_bounds__(NMS_THREADS) void nms_out_kernel(
    const float* __restrict__ logit,
    const float* __restrict__ breg,
    const float* __restrict__ treg,
    const float* __restrict__ prop,
    const int* __restrict__ p_ih,
    const int* __restrict__ p_iw,
    float* __restrict__ out,
    int N, int C, int T, int M, int KC)
{
    int cls = blockIdx.x;
    if (cls >= KC) return;
    int tid = threadIdx.x;
    int laneId = tid & 31;
    int warpId = tid >> 5;

    __shared__ int    s_off[NBKT + 1];
    __shared__ unsigned long long s_key[CAP];
    __shared__ int    s_hist[NBINS];
    __shared__ unsigned long long s_sel[SELCAP];
    __shared__ float4 s_rbox[SELCAP];
    __shared__ float  s_rarea[SELCAP];
    __shared__ float4 a_box[NUM_DET];
    __shared__ float  a_area[NUM_DET];
    __shared__ int    a_gi[NUM_DET];
    __shared__ float  a_sc[NUM_DET];
    __shared__ int    s_cut, s_chunkn, s_nacc, s_selcnt;
    __shared__ int    s_pairm[2][16];

    // ---- bucket prefix (warp 0) ----
    if (warpId == 0) {
        int c0 = min(d_cnt2[cls][2 * laneId],     BCAP);
        int c1 = min(d_cnt2[cls][2 * laneId + 1], BCAP);
        int pair = c0 + c1;
        int incl = pair;
#pragma unroll
        for (int o = 1; o < 32; o <<= 1) {
            int v = __shfl_up_sync(0xFFFFFFFFu, incl, o);
            if (laneId >= o) incl += v;
        }
        s_off[2 * laneId]     = incl - pair;
        s_off[2 * laneId + 1] = incl - c1;
        if (laneId == 31) s_off[NBKT] = incl;
    }
    for (int i = tid; i < NBINS; i += NMS_THREADS) {
        s_hist[i] = d_hist[cls][i];
        d_hist[cls][i] = 0;
    }
    if (tid == 0) s_nacc = 0;
    __syncthreads();

    if (tid < NBKT) d_cnt2[cls][tid] = 0;
    int cnt = s_off[NBKT];
    if (cnt > CAP) cnt = CAP;

    // ---- flat MLP key load ----
    {
        int idxs[8];
        unsigned long long kk[8];
#pragma unroll
        for (int r = 0; r < 8; r++) {
            int i = r * NMS_THREADS + tid;
            idxs[r] = -1;
            if (i < cnt) {
                int lo = 0, hi = NBKT;
#pragma unroll
                for (int b = 0; b < 6; b++) {
                    int mid = (lo + hi) >> 1;
                    if (s_off[mid] <= i) lo = mid; else hi = mid;
                }
                idxs[r] = (lo << 8) | (i - s_off[lo]);
            }
        }
#pragma unroll
        for (int r = 0; r < 8; r++)
            if (idxs[r] >= 0) kk[r] = d_cand_key[cls][idxs[r] >> 8][idxs[r] & 255];
#pragma unroll
        for (int r = 0; r < 8; r++)
            if (idxs[r] >= 0) s_key[r * NMS_THREADS + tid] = kk[r];
    }
    __syncthreads();

    // ---- incremental descending-score chunks ----
    float4 rb[4];
    float  ra[4];
#pragma unroll
    for (int s = 0; s < 4; s++) { rb[s] = make_float4(0,0,0,0); ra[s] = 0.0f; }
    int naccr = 0;

    int hi_cut = NBINS;
    bool fb = false;

    while (naccr < NUM_DET && hi_cut > 0 && !fb) {
        if (warpId == 0) {
            int acc = 0, cut = 0, chn = 0;
            bool found = false;
            int baseStart = ((hi_cut - 1) >> 5) << 5;
            for (int base = baseStart; base >= 0; base -= 32) {
                int bin = base + laneId;
                int v = (bin < hi_cut) ? s_hist[bin] : 0;
                int tot = v;
#pragma unroll
                for (int o = 16; o; o >>= 1) tot += __shfl_xor_sync(0xFFFFFFFFu, tot, o);
                if (acc + tot >= CHUNK_TARGET) {
                    int suf = v;
#pragma unroll
                    for (int o = 1; o < 32; o <<= 1) {
                        int t = __shfl_down_sync(0xFFFFFFFFu, suf, o);
                        if (laneId + o < 32) suf += t;
                    }
                    unsigned bal = __ballot_sync(0xFFFFFFFFu, acc + suf >= CHUNK_TARGET);
                    int L = 31 - __clz(bal);
                    cut = base + L;
                    chn = acc + __shfl_sync(0xFFFFFFFFu, suf, L);
                    found = true;
                    break;
                }
                acc += tot;
            }
            if (!found) { cut = 0; chn = acc; }
            if (laneId == 0) { s_cut = cut; s_chunkn = chn; s_selcnt = 0; }
        }
        __syncthreads();
        int cutv = s_cut;
        int chn  = s_chunkn;

        if (chn > SELCAP) { fb = true; break; }

        if (chn > 0) {
            // -- gather chunk keys (warp-aggregated shared atomic) --
            {
                int iters = (cnt + NMS_THREADS - 1) / NMS_THREADS;
                for (int r = 0; r < iters; r++) {
                    int i = r * NMS_THREADS + tid;
                    bool match = false;
                    unsigned long long k = 0ull;
                    if (i < cnt) {
                        k = s_key[i];
                        int bin = min((int)((unsigned)(k >> 32) >> 16) - HBASE, NBINS - 1);
                        match = (bin >= cutv && bin < hi_cut);
                    }
                    unsigned bal = __ballot_sync(0xFFFFFFFFu, match);
                    if (bal) {
                        int base = 0;
                        if (laneId == 0) base = atomicAdd(&s_selcnt, __popc(bal));
                        base = __shfl_sync(0xFFFFFFFFu, base, 0);
                        if (match)
                            s_sel[base + __popc(bal & ((1u << laneId) - 1u))] = k;
                    }
                }
            }
            __syncthreads();
            chn = min(chn, s_selcnt);

            if (chn <= NMS_THREADS) {
                unsigned long long kr = (tid < chn) ? s_sel[tid] : 0ull;
#pragma unroll
                for (int k = 2; k <= NMS_THREADS; k <<= 1) {
#pragma unroll
                    for (int j = k >> 1; j > 0; j >>= 1) {
                        unsigned long long o;
                        if (j >= 32) {
                            s_sel[tid] = kr;
                            __syncthreads();
                            o = s_sel[tid ^ j];
                            __syncthreads();
                        } else {
                            o = __shfl_xor_sync(0xFFFFFFFFu, kr, j);
                        }
                        bool keepMax = ((tid & k) == 0) == ((tid & j) == 0);
                        kr = keepMax ? u64max(kr, o) : u64min(kr, o);
                    }
                }
                s_sel[tid] = kr;
                __syncthreads();
            } else {
                for (int i = chn + tid; i < SELCAP; i += NMS_THREADS) s_sel[i] = 0ull;
                __syncthreads();
                for (int k = 2; k <= SELCAP; k <<= 1) {
                    for (int j = k >> 1; j > 0; j >>= 1) {
                        for (int idx = tid; idx < SELCAP; idx += NMS_THREADS) {
                            int l = idx ^ j;
                            if (l > idx) {
                                unsigned long long a = s_sel[idx];
                                unsigned long long b = s_sel[l];
                                bool up = ((idx & k) == 0);
                                if (up ? (a < b) : (a > b)) { s_sel[idx] = b; s_sel[l] = a; }
                            }
                        }
                        __syncthreads();
                    }
                }
            }

            for (int r = tid; r < chn; r += NMS_THREADS) {
                int slot = (int)(s_sel[r] & 0xFFFFu);
                float4 bx = d_cand_box[cls][slot >> 8][slot & 255];
                s_rbox[r]  = bx;
                s_rarea[r] = (bx.z - bx.x) * (bx.w - bx.y);
            }
            __syncthreads();

            // -- 16-wide single-barrier tiles --
            for (int tb = 0; tb < chn && naccr < NUM_DET; tb += 16) {
                int buf = (tb >> 4) & 1;
                int i1 = tb + warpId;
                int i2 = tb + 8 + warpId;

                bool sup1 = false, pair1 = false;
                bool sup2 = false, pair2 = false;
                if (i1 < chn) {
                    float4 b1 = s_rbox[i1];
                    float ca1 = s_rarea[i1];
#pragma unroll
                    for (int s = 0; s < 4; s++) {
                        int j = s * 32 + laneId;
                        if (j < naccr && iou_over(rb[s], ra[s], b1, ca1)) sup1 = true;
                    }
                    if (laneId < warpId)
                        pair1 = iou_over(s_rbox[tb + laneId], s_rarea[tb + laneId], b1, ca1);
                }
                if (i2 < chn) {
                    float4 b2 = s_rbox[i2];
                    float ca2 = s_rarea[i2];
#pragma unroll
                    for (int s = 0; s < 4; s++) {
                        int j = s * 32 + laneId;
                        if (j < naccr && iou_over(rb[s], ra[s], b2, ca2)) sup2 = true;
                    }
                    if (laneId < 8 + warpId)
                        pair2 = iou_over(s_rbox[tb + laneId], s_rarea[tb + laneId], b2, ca2);
                }
                unsigned bal1 = __ballot_sync(0xFFFFFFFFu, pair1) & ((1u << warpId) - 1u);
                unsigned bal2 = __ballot_sync(0xFFFFFFFFu, pair2) & ((1u << (8 + warpId)) - 1u);
                bool sa1 = __any_sync(0xFFFFFFFFu, sup1);
                bool sa2 = __any_sync(0xFFFFFFFFu, sup2);
                if (laneId == 0) {
                    s_pairm[buf][warpId]     = (int)bal1 | (sa1 ? 0x10000 : 0);
                    s_pairm[buf][8 + warpId] = (int)bal2 | (sa2 ? 0x10000 : 0);
                }
                __syncthreads();       // the only barrier in the tile

                // streamlined resolve: uncapped greedy, then exact truncation
                int lim = min(16, chn - tb);
                unsigned kept = 0;
                int newn = 0;
                for (int t = 0; t < lim; t++) {
                    int pmv = s_pairm[buf][t];
                    if (!(pmv & 0x10000) && !((unsigned)pmv & kept)) {
                        kept |= 1u << t;
                        newn++;
                    }
                }
                if (naccr + newn > NUM_DET) {
                    int allow = NUM_DET - naccr;
                    unsigned kk = 0;
                    for (int a2 = 1; a2 <= allow; a2++)
                        kk |= 1u << __fns(kept, 0, a2);
                    kept = kk;
                    newn = allow;
                }

                // append accepted (warp 0, lanes 0-15)
                if (warpId == 0 && laneId < 16 && ((kept >> laneId) & 1u)) {
                    int pos = naccr + __popc(kept & ((1u << laneId) - 1u));
                    int ii = tb + laneId;
                    unsigned long long k = s_sel[ii];
                    a_box[pos]  = s_rbox[ii];
                    a_area[pos] = s_rarea[ii];
                    a_gi[pos]   = (int)(0xFFFFu - ((unsigned)(k >> 16) & 0xFFFFu));
                    a_sc[pos]   = __uint_as_float((unsigned)(k >> 32));
                }

                // replica refresh via find-nth-set-bit (no loop over kept bits)
#pragma unroll
                for (int s = 0; s < 4; s++) {
                    int pos = s * 32 + laneId;
                    if (pos >= naccr && pos < naccr + newn) {
                        int t = (int)__fns(kept, 0, pos - naccr + 1);
                        rb[s] = s_rbox[tb + t];
                        ra[s] = s_rarea[tb + t];
                    }
                }
                naccr += newn;
            }
            if (tid == 0) s_nacc = naccr;
            __syncthreads();
        }

        hi_cut = cutv;
        __syncthreads();
    }

    if (fb) {
        // compact exact fallback: serial argmax greedy (warp 0)
        if (tid == 0) s_nacc = 0;
        __syncthreads();
        if (warpId == 0) {
            int nacc = 0;
            while (nacc < NUM_DET) {
                unsigned long long bk = 0ull;
                for (int i = laneId; i < cnt; i += 32) bk = u64max(bk, s_key[i]);
#pragma unroll
                for (int o = 16; o; o >>= 1)
                    bk = u64max(bk, __shfl_down_sync(0xFFFFFFFFu, bk, o));
                bk = __shfl_sync(0xFFFFFFFFu, bk, 0);
                if (bk == 0ull) break;
                int slot = (int)(bk & 0xFFFFu);
                float4 b = d_cand_box[cls][slot >> 8][slot & 255];
                float carea = (b.z - b.x) * (b.w - b.y);
                if (laneId == 0) {
                    a_box[nacc]  = b;
                    a_area[nacc] = carea;
                    a_gi[nacc]   = (int)(0xFFFFu - ((unsigned)(bk >> 16) & 0xFFFFu));
                    a_sc[nacc]   = __uint_as_float((unsigned)(bk >> 32));
                }
                __syncwarp();
                for (int i = laneId; i < cnt; i += 32) {
                    unsigned long long k = s_key[i];
                    if (k != 0ull) {
                        int sl = (int)(k & 0xFFFFu);
                        float4 bb = d_cand_box[cls][sl >> 8][sl & 255];
                        float aa = (bb.z - bb.x) * (bb.w - bb.y);
                        if (iou_over(b, carea, bb, aa)) s_key[i] = 0ull;
                    }
                }
                nacc++;
                __syncwarp();
            }
            if (laneId == 0) s_nacc = nacc;
        }
        __syncthreads();
    }
    __syncthreads();
    int ndet = s_nacc;

    // ---- fused output ----
    float W = (float)(*p_iw);
    float H = (float)(*p_ih);
    int clabel = cls + 1;

    size_t OFF_LBL = (size_t)M * 4;
    size_t OFF_SC  = OFF_LBL + M;
    size_t OFF_FUT = OFF_SC + M;
    size_t OFF_VAL = OFF_FUT + (size_t)T * M * 4;

    for (int d = tid; d < NUM_DET; d += NMS_THREADS) {
        bool v = (d < ndet);
        int g = v ? a_gi[d] : 0;
        int m = cls * NUM_DET + d;

        float4 p = ((const float4*)prop)[g];
        const float4 td0 = *(const float4*)(treg + (((size_t)0 * N + g) * C + clabel) * 4);
        const float4 td1 = *(const float4*)(treg + (((size_t)1 * N + g) * C + clabel) * 4);
        const float4 td2 = *(const float4*)(treg + (((size_t)2 * N + g) * C + clabel) * 4);

        float4 obox;
        float scv;
        if (v) {
            obox = a_box[d];
            scv  = a_sc[d];
        } else {
            float lg  = logit[clabel];
            scv = expf(lg - d_row_max0) / d_row_den0;
            const float4 dd = *(const float4*)(breg + (size_t)clabel * 4);
            float x1, y1, x2, y2;
            decode_box(dd.x, dd.y, dd.z, dd.w, p.x, p.y, p.z, p.w, x1, y1, x2, y2);
            obox = make_float4(clipf(x1, W), clipf(y1, H), clipf(x2, W), clipf(y2, H));
        }

        ((float4*)out)[m] = obox;
        out[OFF_LBL + m] = (float)clabel;
        out[OFF_SC + m]  = scv;
        out[OFF_VAL + m] = v ? 1.0f : 0.0f;

        float cx1 = p.x, cy1 = p.y, cx2 = p.z, cy2 = p.w;
        float4 tds[3] = {td0, td1, td2};
#pragma unroll
        for (int t = 0; t < 3; t++) {
            float nx1, ny1, nx2, ny2;
            decode_box(tds[t].x, tds[t].y, tds[t].z, tds[t].w,
                       cx1, cy1, cx2, cy2, nx1, ny1, nx2, ny2);
            float4 of = make_float4(clipf(nx1, W), clipf(ny1, H), clipf(nx2, W), clipf(ny2, H));
            ((float4*)(out + OFF_FUT))[(size_t)t * M + m] = of;
            cx1 = nx1; cy1 = ny1; cx2 = nx2; cy2 = ny2;
        }
    }
}

// ---------------- launch ----------------
extern "C" void kernel_launch(void* const* d_in, const int* in_sizes, int n_in,
                              void* d_out, int out_size)
{
    const float* logit = (const float*)d_in[0];
    const float* breg  = (const float*)d_in[1];
    const float* treg  = (const float*)d_in[2];
    const float* prop  = (const float*)d_in[3];
    const int*   p_ih  = (const int*)d_in[4];
    const int*   p_iw  = (const int*)d_in[5];

    int N = in_sizes[3] / 4;
    int C = in_sizes[0] / N;
    int T = in_sizes[2] / in_sizes[1];
    int KC = C - 1;
    int M = KC * NUM_DET;

    int warpsPerBlock = 8;
    int blocks = (N + warpsPerBlock - 1) / warpsPerBlock;
    if (C == 91) {
        score_extract_t<91><<<blocks, 256>>>(logit, breg, prop, p_ih, p_iw, N, C);
    } else {
        score_extract_t<0><<<blocks, 256>>>(logit, breg, prop, p_ih, p_iw, N, C);
    }

    int nmsGrid = (KC < MIN_GRID) ? MIN_GRID : KC;
    nms_out_kernel<<<nmsGrid, NMS_THREADS>>>(logit, breg, treg, prop, p_ih, p_iw,
                                             (float*)d_out, N, C, T, M, KC);
}